// round 11
// baseline (speedup 1.0000x reference)
#include <cuda_runtime.h>
#include <cstdint>

// ---------------------------------------------------------------------------
// ImageGraphConvolution:
//   support = x @ W + b                      [N,1024] @ [1024,14] + [14]
//   out[r]  = sum_e{row[e]==r} vals[e] * support[col[e]]   (COO segment-sum)
//
// Strategy (design frozen pending first successful bench):
//   - GEMM with packed fma.rn.f32x2 (sm_10x FFMA2). W staged in smem
//     (warp-uniform LDS broadcasts beat the 1.82cyc/SM LDG issue floor);
//     x double-buffered into smem via cp.async, conflict-free stride-20.
//   - support and scatter target padded to 16-float (64B) rows so the
//     scatter uses red.global.add.{v4,v2}.f32: 4 L2 reductions/edge vs 14.
//   - SpMM processes 4 edges/thread with vectorized index loads.
//   - final compaction copy 16 -> 14 stride into d_out (streaming stores).
// ---------------------------------------------------------------------------

#define FEAT 1024
#define ODIM 14
#define PAD  16          // padded row stride (floats) -> 64B, 16B-aligned
#define TPB  128         // threads per block (GEMM)
#define RPT  2           // rows per thread
#define RPB  (TPB * RPT) // 256 rows per block
#define KB   16          // k-chunk staged through smem
#define XS_STRIDE (KB + 4)  // stride 20: LDS.128 phase covers all 32 banks once
#define STAGE_OPS ((RPB * KB / 4) / TPB)   // cp.async (16B) ops per thread = 8

#define W_FLOATS (ODIM * FEAT)                         // 14336
#define XS_FLOATS (RPB * XS_STRIDE)                    // 5120 per buffer
#define GEMM_SMEM_BYTES ((W_FLOATS + 2 * XS_FLOATS) * 4)  // 98304 B

#define MAXN 100000

// Scratch (no allocation allowed -> __device__ globals)
__device__ __align__(16) float g_support[MAXN * PAD];   // 6.4 MB
__device__ __align__(16) float g_out_pad[MAXN * PAD];   // 6.4 MB
__device__ __align__(16) float g_Wt[W_FLOATS];          // W transposed [j][k]

// ---- packed f32x2 FMA (sm_10x; FFMA2 only reachable via PTX) ----
__device__ __forceinline__ unsigned long long pk2(float lo, float hi) {
    unsigned long long r;
    asm("mov.b64 %0, {%1, %2};" : "=l"(r) : "f"(lo), "f"(hi));
    return r;
}
__device__ __forceinline__ void fma2(unsigned long long& d,
                                     unsigned long long a,
                                     unsigned long long b) {
    asm("fma.rn.f32x2 %0, %1, %2, %0;" : "+l"(d) : "l"(a), "l"(b));
}
__device__ __forceinline__ float sum2(unsigned long long v) {
    float lo, hi;
    asm("mov.b64 {%0, %1}, %2;" : "=f"(lo), "=f"(hi) : "l"(v));
    return lo + hi;
}

// ---- vector reductions to global (sm_90+): one L2 red op per 16B / 8B.
// PTX ISA grammar: red{.sem}{.scope}{.global}.op{...}.vec_32_bit -> the
// mnemonics below are conformant. Fallback if ptxas rejects: scalar
// atomicAdd per component inside these two wrappers. ----
__device__ __forceinline__ void red_add_v4(float* p, float a, float b,
                                           float c, float d) {
    asm volatile("red.global.add.v4.f32 [%0], {%1, %2, %3, %4};"
                 :: "l"(p), "f"(a), "f"(b), "f"(c), "f"(d)
                 : "memory");
}
__device__ __forceinline__ void red_add_v2(float* p, float a, float b) {
    asm volatile("red.global.add.v2.f32 [%0], {%1, %2};"
                 :: "l"(p), "f"(a), "f"(b)
                 : "memory");
}

// ---- cp.async 16B ----
__device__ __forceinline__ void cp_async16(void* smem_dst, const void* gsrc) {
    uint32_t d = (uint32_t)__cvta_generic_to_shared(smem_dst);
    asm volatile("cp.async.ca.shared.global [%0], [%1], 16;"
                 :: "r"(d), "l"(gsrc));
}
__device__ __forceinline__ void cp_commit() {
    asm volatile("cp.async.commit_group;");
}
template <int N>
__device__ __forceinline__ void cp_wait() {
    asm volatile("cp.async.wait_group %0;" :: "n"(N));
}

// ---------------------------------------------------------------------------
// Transpose W [1024,14] -> g_Wt [14,1024]
// ---------------------------------------------------------------------------
__global__ void transpose_w_kernel(const float* __restrict__ W) {
    int i = blockIdx.x * blockDim.x + threadIdx.x;
    if (i < ODIM * FEAT) {
        int j = i / FEAT;
        int k = i % FEAT;
        g_Wt[i] = W[k * ODIM + j];
    }
}

// ---------------------------------------------------------------------------
// GEMM: 2 rows/thread, 14 packed-f32x2 accumulators per row.
// W resident in smem (uniform LDS broadcasts); x double-buffered via
// cp.async. Also zeroes the g_out_pad rows this block owns.
// ---------------------------------------------------------------------------
__global__ void __launch_bounds__(TPB)
gemm_kernel(const float* __restrict__ x, const float* __restrict__ b, int nrows) {
    extern __shared__ __align__(16) float smem[];
    float* Ws  = smem;                      // 14336 floats (56 KB)
    float* xs0 = smem + W_FLOATS;           // buffer 0
    float* xs1 = xs0 + XS_FLOATS;           // buffer 1

    const int t    = threadIdx.x;
    const int row0 = blockIdx.x * RPB;
    const int rA   = row0 + t;
    const int rB   = row0 + TPB + t;

    // Stage one 16-k chunk. Out-of-range rows clamp to a valid address;
    // their accumulators are discarded at the guarded epilogue.
    auto issue_stage = [&](float* bufp, int k0) {
#pragma unroll
        for (int i = 0; i < STAGE_OPS; i++) {
            int idx = i * TPB + t;
            int r = idx >> 2;      // KB/4 = 4 float4 per row
            int q = idx & 3;
            int gr = row0 + r;
            if (gr >= nrows) gr = nrows - 1;
            cp_async16(bufp + r * XS_STRIDE + q * 4,
                       x + (size_t)gr * FEAT + k0 + q * 4);
        }
        cp_commit();
    };

    // Kick off first x stage, then fill W while it flies.
    issue_stage(xs0, 0);
#pragma unroll 4
    for (int i = t; i < W_FLOATS / 4; i += TPB)
        ((float4*)Ws)[i] = ((const float4*)g_Wt)[i];

    unsigned long long accA[ODIM], accB[ODIM];
#pragma unroll
    for (int j = 0; j < ODIM; j++) { accA[j] = 0ull; accB[j] = 0ull; }

    int buf = 0;
    for (int k0 = 0; k0 < FEAT; k0 += KB, buf ^= 1) {
        if (k0 + KB < FEAT) {
            issue_stage(buf ? xs0 : xs1, k0 + KB);
            cp_wait<1>();
        } else {
            cp_wait<0>();
        }
        __syncthreads();   // x chunk visible to all; also fences Ws on iter 0

        const float* xsc = buf ? xs1 : xs0;
#pragma unroll
        for (int kk = 0; kk < KB; kk += 4) {
            float4 xa = *(const float4*)(xsc + t * XS_STRIDE + kk);
            float4 xb = *(const float4*)(xsc + (TPB + t) * XS_STRIDE + kk);
            unsigned long long xa0 = pk2(xa.x, xa.y), xa1 = pk2(xa.z, xa.w);
            unsigned long long xb0 = pk2(xb.x, xb.y), xb1 = pk2(xb.z, xb.w);
#pragma unroll
            for (int j = 0; j < ODIM; j++) {
                float4 w = *(const float4*)(Ws + j * FEAT + k0 + kk);
                unsigned long long w0 = pk2(w.x, w.y), w1 = pk2(w.z, w.w);
                fma2(accA[j], xa0, w0);
                fma2(accA[j], xa1, w1);
                fma2(accB[j], xb0, w0);
                fma2(accB[j], xb1, w1);
            }
        }
        __syncthreads();   // protect buffer reuse by next iteration's cp.async
    }

    float bias[ODIM];
#pragma unroll
    for (int j = 0; j < ODIM; j++) bias[j] = __ldg(b + j);

    const float4 z4 = make_float4(0.f, 0.f, 0.f, 0.f);
    if (rA < nrows) {
        float* s = g_support + (size_t)rA * PAD;
#pragma unroll
        for (int j = 0; j < ODIM; j++)
            s[j] = sum2(accA[j]) + bias[j];
        s[14] = 0.f; s[15] = 0.f;
        float4* o = (float4*)(g_out_pad + (size_t)rA * PAD);
        o[0] = z4; o[1] = z4; o[2] = z4; o[3] = z4;
    }
    if (rB < nrows) {
        float* s = g_support + (size_t)rB * PAD;
#pragma unroll
        for (int j = 0; j < ODIM; j++)
            s[j] = sum2(accB[j]) + bias[j];
        s[14] = 0.f; s[15] = 0.f;
        float4* o = (float4*)(g_out_pad + (size_t)rB * PAD);
        o[0] = z4; o[1] = z4; o[2] = z4; o[3] = z4;
    }
}

// ---------------------------------------------------------------------------
// COO SpMM: 4 edges per thread with vectorized index/value loads.
// Per edge: gather 64B support row (aligned, L2-resident), scatter with
// 3x red.v4 + 1x red.v2 (4 L2 ops).
// ---------------------------------------------------------------------------
__device__ __forceinline__ void spmm_one_edge(float v, int r, int c) {
    const float4* s = (const float4*)(g_support + (size_t)c * PAD);
    float*        o = g_out_pad + (size_t)r * PAD;

    float4 s0 = __ldg(s + 0);
    float4 s1 = __ldg(s + 1);
    float4 s2 = __ldg(s + 2);
    float2 s3 = __ldg((const float2*)(s + 3));  // lanes 12,13 (14,15 are pads)

    red_add_v4(o + 0,  v * s0.x, v * s0.y, v * s0.z, v * s0.w);
    red_add_v4(o + 4,  v * s1.x, v * s1.y, v * s1.z, v * s1.w);
    red_add_v4(o + 8,  v * s2.x, v * s2.y, v * s2.z, v * s2.w);
    red_add_v2(o + 12, v * s3.x, v * s3.y);
}

__global__ void __launch_bounds__(256)
spmm_kernel(const float* __restrict__ vals,
            const int*   __restrict__ rows,
            const int*   __restrict__ cols,
            int nE) {
    int base = (blockIdx.x * blockDim.x + threadIdx.x) * 4;
    if (base >= nE) return;

    if (base + 4 <= nE) {
        float4 v4 = __ldg((const float4*)(vals + base));
        int4   r4 = __ldg((const int4*)(rows + base));
        int4   c4 = __ldg((const int4*)(cols + base));
        spmm_one_edge(v4.x, r4.x, c4.x);
        spmm_one_edge(v4.y, r4.y, c4.y);
        spmm_one_edge(v4.z, r4.z, c4.z);
        spmm_one_edge(v4.w, r4.w, c4.w);
    } else {
        for (int e = base; e < nE; e++)
            spmm_one_edge(__ldg(vals + e), __ldg(rows + e), __ldg(cols + e));
    }
}

// ---------------------------------------------------------------------------
// Compact stride-16 accumulator into stride-14 output. Output is written
// once and never re-read -> streaming store (evict-first) keeps L2 clean.
// ---------------------------------------------------------------------------
__global__ void __launch_bounds__(256)
compact_kernel(float* __restrict__ out, int n) {   // n = nrows*ODIM
    int i = blockIdx.x * blockDim.x + threadIdx.x;
    if (i < n) {
        int r = i / ODIM;
        int j = i - r * ODIM;
        float v = g_out_pad[(size_t)r * PAD + j];
        __stcs(out + i, v);
    }
}

// ---------------------------------------------------------------------------
extern "C" void kernel_launch(void* const* d_in, const int* in_sizes, int n_in,
                              void* d_out, int out_size) {
    const float* x    = (const float*)d_in[0];
    const float* W    = (const float*)d_in[1];
    const float* b    = (const float*)d_in[2];
    const float* vals = (const float*)d_in[3];
    const int*   rows = (const int*)d_in[4];
    const int*   cols = (const int*)d_in[5];
    float*       out  = (float*)d_out;

    int nrows = in_sizes[0] / FEAT;
    int nE    = in_sizes[3];

    // Idempotent, non-stream, capture-safe; no static guard (determinism rule).
    cudaFuncSetAttribute(gemm_kernel,
                         cudaFuncAttributeMaxDynamicSharedMemorySize,
                         GEMM_SMEM_BYTES);

    transpose_w_kernel<<<(ODIM * FEAT + 255) / 256, 256>>>(W);
    gemm_kernel<<<(nrows + RPB - 1) / RPB, TPB, GEMM_SMEM_BYTES>>>(x, b, nrows);
    int nq = (nE + 3) / 4;
    spmm_kernel<<<(nq + 255) / 256, 256>>>(vals, rows, cols, nE);
    compact_kernel<<<(nrows * ODIM + 255) / 256, 256>>>(out, nrows * ODIM);
}